// round 13
// baseline (speedup 1.0000x reference)
#include <cuda_runtime.h>
#include <cuda_fp16.h>
#include <cstdint>

// TensorTrainLinear: out = x @ W + bias.
// Single fused kernel: blocks [0,2048) convert x->fp16; blocks [2048,6144)
// build W (fp16, [o][in]) from TT cores; blocks [6144,6656) run the fp16
// single-product GEMM, gated on a device counter until prep completes.
// rel_err 2.9e-4 < 1e-3. Counters self-reset -> deterministic graph replays.

#define KDIM 4096
#define NDIM 4096
#define MDIM 2048

#define NB_X    2048
#define NB_W    4096
#define NB_PREP (NB_X + NB_W)    // 6144
#define NB_GEMM 512
#define NB_ALL  (NB_PREP + NB_GEMM)

// ---- device scratch (no runtime allocation allowed) ----
__device__ __half g_xh[(size_t)MDIM * KDIM];             // 16 MB
__device__ __half g_wt[(size_t)NDIM * KDIM];             // 32 MB  [o][in]
__device__ int    g_ready = 0;                           // prep blocks done
__device__ int    g_done  = 0;                           // gemm blocks done

// ---------------------------------------------------------------------------
// helpers
// ---------------------------------------------------------------------------
__device__ __forceinline__ uint32_t smem_u32(const void* p) {
    uint32_t a;
    asm("{ .reg .u64 t; cvta.to.shared.u64 t, %1; cvt.u32.u64 %0, t; }"
        : "=r"(a) : "l"(p));
    return a;
}

__device__ __forceinline__ void cp16(uint32_t saddr, const void* gaddr) {
    asm volatile("cp.async.cg.shared.global [%0], [%1], 16;\n"
                 :: "r"(saddr), "l"(gaddr));
}
__device__ __forceinline__ void cp_commit() {
    asm volatile("cp.async.commit_group;\n" ::: "memory");
}

__device__ __forceinline__ void ldm4(uint32_t& r0, uint32_t& r1,
                                     uint32_t& r2, uint32_t& r3,
                                     uint32_t addr) {
    asm volatile("ldmatrix.sync.aligned.m8n8.x4.shared.b16 {%0,%1,%2,%3}, [%4];"
                 : "=r"(r0), "=r"(r1), "=r"(r2), "=r"(r3) : "r"(addr));
}

__device__ __forceinline__ void mma16816(float* c, const uint32_t* a,
                                         const uint32_t* b) {
    asm volatile(
        "mma.sync.aligned.m16n8k16.row.col.f32.f16.f16.f32 "
        "{%0,%1,%2,%3}, {%4,%5,%6,%7}, {%8,%9}, {%0,%1,%2,%3};"
        : "+f"(c[0]), "+f"(c[1]), "+f"(c[2]), "+f"(c[3])
        : "r"(a[0]), "r"(a[1]), "r"(a[2]), "r"(a[3]), "r"(b[0]), "r"(b[1]));
}

// ---------------------------------------------------------------------------
#define TILE_BYTES  16384              // 128 rows x 128B
#define STAGE_BYTES (2 * TILE_BYTES)   // 32768 (A, B)
#define NSTAGE      3
#define SMEM_TOTAL  (NSTAGE * STAGE_BYTES)  // 98304

__device__ __forceinline__ void load_tile(uint32_t sb, int stage, int t,
                                          int c, int blk, int tid) {
    const __half* gbase =
        (t == 0 ? g_xh + ((size_t)blk * 128) * KDIM
                : g_wt + ((size_t)blk * 128) * KDIM) + (size_t)c * 64;
    const uint32_t ts = sb + stage * STAGE_BYTES + t * TILE_BYTES;
    const char* gb = (const char*)gbase;
#pragma unroll
    for (int i = 0; i < 4; ++i) {
        const int e   = tid + i * 256;   // 0..1023
        const int row = e >> 3;          // 0..127
        const int seg = e & 7;           // 16B segment in 128B row
        const uint32_t off = row * 128 + seg * 16;
        const uint32_t sw  = off ^ ((off >> 3) & 0x70);
        cp16(ts + sw, gb + (size_t)row * (KDIM * 2) + seg * 16);
    }
}

__global__ void __launch_bounds__(256, 2)
tt_fused(const float* __restrict__ x,
         const float* __restrict__ core0,
         const float* __restrict__ core1,
         const float* __restrict__ core2,
         const float* __restrict__ bias,
         float* __restrict__ out) {
    extern __shared__ __align__(128) char smem[];
    const int tid = threadIdx.x;
    const int bid = blockIdx.x;

    // =========================== x-convert role ===========================
    if (bid < NB_X) {
        const size_t base = ((size_t)bid * 256 + tid) * 16;
#pragma unroll
        for (int h = 0; h < 2; ++h) {
            const size_t b8 = base + h * 8;
            float4 v0 = *(const float4*)(x + b8);
            float4 v1 = *(const float4*)(x + b8 + 4);
            float f[8] = {v0.x, v0.y, v0.z, v0.w, v1.x, v1.y, v1.z, v1.w};
            __half hh[8];
#pragma unroll
            for (int i = 0; i < 8; ++i) hh[i] = __float2half(f[i]);
            *(uint4*)(g_xh + b8) = *(uint4*)hh;
        }
        __threadfence();
        __syncthreads();
        if (tid == 0) atomicAdd(&g_ready, 1);
        return;
    }

    // ============================ W-build role ============================
    if (bid < NB_PREP) {
        float* s_c2t = (float*)smem;                 // [r][o3][i3]  16 KB
        float* s_m01 = (float*)(smem + 16384);       // [i2][r]       1 KB
        float* s_c0  = (float*)(smem + 17408);       //              64 B

        const int b   = bid - NB_X;            // 0..4095
        const int ohi = b >> 4;                // o1*16 + o2
        const int o2  = ohi & 15;
        const int i1  = b & 15;

#pragma unroll
        for (int i = 0; i < 16; ++i) {
            const int idx = tid + i * 256;     // src = r*256 + i3*16 + o3
            const int r = idx >> 8, i3s = (idx >> 4) & 15, o3s = idx & 15;
            s_c2t[r * 256 + o3s * 16 + i3s] = core2[idx];
        }
        if (tid < 16) s_c0[tid] = core0[i1 * 256 + (ohi >> 4) * 16 + tid];
        __syncthreads();

        {
            const int i2s = tid >> 4, r = tid & 15;
            const float* c1p = core1 + i2s * 256 + o2 * 16 + r;
            float a0 = 0.f, a1 = 0.f;
#pragma unroll
            for (int q = 0; q < 16; q += 2) {
                a0 = fmaf(s_c0[q],     c1p[q * 4096],       a0);
                a1 = fmaf(s_c0[q + 1], c1p[(q + 1) * 4096], a1);
            }
            s_m01[tid] = a0 + a1;
        }
        __syncthreads();

        const int i2 = tid >> 4, i3 = tid & 15;
        const int in = i1 * 256 + i2 * 16 + i3;
        float m01[16];
#pragma unroll
        for (int r = 0; r < 16; ++r) m01[r] = s_m01[i2 * 16 + r];

#pragma unroll
        for (int o3 = 0; o3 < 16; ++o3) {
            float a0 = 0.f, a1 = 0.f;
            const float* c2p = s_c2t + o3 * 16 + i3;
#pragma unroll
            for (int r = 0; r < 16; r += 2) {
                a0 = fmaf(m01[r],     c2p[r * 256],       a0);
                a1 = fmaf(m01[r + 1], c2p[(r + 1) * 256], a1);
            }
            g_wt[(size_t)(ohi * 16 + o3) * KDIM + in] = __float2half(a0 + a1);
        }
        __threadfence();
        __syncthreads();
        if (tid == 0) atomicAdd(&g_ready, 1);
        return;
    }

    // ============================= GEMM role ==============================
    // Gate: wait until all prep blocks have released.
    if (tid == 0) {
        while (atomicAdd(&g_ready, 0) < NB_PREP) __nanosleep(64);
        __threadfence();
    }
    __syncthreads();

    const uint32_t sb = smem_u32(smem);
    const int lane = tid & 31;
    const int wid = tid >> 5;
    const int warpM = wid >> 2;      // 0..1
    const int warpN = wid & 3;       // 0..3
    const int g = bid - NB_PREP;     // 0..511
    const int bn = g & 31, bm = g >> 5;

    float acc[4][4][4];
#pragma unroll
    for (int i = 0; i < 4; ++i)
#pragma unroll
        for (int j = 0; j < 4; ++j)
#pragma unroll
            for (int k = 0; k < 4; ++k) acc[i][j][k] = 0.f;

    // SW128: store XORs addr bits 4-6 with row bits 0-2. Load-side:
    // sw = (lane&7) << 4 (all other row terms are multiples of 8).
    const uint32_t sw = (uint32_t)((lane & 7) << 4);
    const uint32_t aRowOff = (uint32_t)(warpM * 64 + (lane & 15)) * 128;
    const uint32_t aColB   = (uint32_t)((lane >> 4) << 4);
    const uint32_t bRowOff =
        (uint32_t)(warpN * 32 + (lane & 7) + ((lane >> 4) & 1) * 8) * 128;
    const uint32_t bColB = (uint32_t)(((lane >> 3) & 1) << 4);

    load_tile(sb, 0, 0, 0, bm, tid);
    load_tile(sb, 0, 1, 0, bn, tid);
    cp_commit();
    load_tile(sb, 1, 0, 1, bm, tid);
    load_tile(sb, 1, 1, 1, bn, tid);
    cp_commit();

    const int KT = KDIM / 64;  // 64
    int st = 0;
    for (int c = 0; c < KT; ++c) {
        if (c + 1 < KT) asm volatile("cp.async.wait_group 1;" ::: "memory");
        else            asm volatile("cp.async.wait_group 0;" ::: "memory");
        __syncthreads();

        const bool pf = (c + 2 < KT);
        int st2 = st + 2; if (st2 >= NSTAGE) st2 -= NSTAGE;
        if (pf) load_tile(sb, st2, 0, c + 2, bm, tid);

        const uint32_t sA = sb + st * STAGE_BYTES;
        const uint32_t sB = sA + TILE_BYTES;

        // B fragments double-buffered across the 4 k-steps
        uint32_t bw[2][4][2];
        {
            const uint32_t bco0 = bColB ^ sw;
#pragma unroll
            for (int np = 0; np < 2; ++np) {
                const uint32_t no = bRowOff + np * 16 * 128 + bco0;
                uint32_t r0, r1, r2, r3;
                ldm4(r0, r1, r2, r3, sB + no);
                bw[0][np * 2][0] = r0; bw[0][np * 2][1] = r1;
                bw[0][np * 2 + 1][0] = r2; bw[0][np * 2 + 1][1] = r3;
            }
        }

#pragma unroll
        for (int ks = 0; ks < 4; ++ks) {
            const int cur = ks & 1;
            const uint32_t aco = (aColB + ks * 32) ^ sw;

            if (ks < 3) {
                const uint32_t bco = (bColB + (ks + 1) * 32) ^ sw;
#pragma unroll
                for (int np = 0; np < 2; ++np) {
                    const uint32_t no = bRowOff + np * 16 * 128 + bco;
                    uint32_t r0, r1, r2, r3;
                    ldm4(r0, r1, r2, r3, sB + no);
                    bw[cur ^ 1][np * 2][0] = r0; bw[cur ^ 1][np * 2][1] = r1;
                    bw[cur ^ 1][np * 2 + 1][0] = r2; bw[cur ^ 1][np * 2 + 1][1] = r3;
                }
            }

#pragma unroll
            for (int mt = 0; mt < 4; ++mt) {
                uint32_t ah[4];
                ldm4(ah[0], ah[1], ah[2], ah[3],
                     sA + aRowOff + mt * 16 * 128 + aco);
#pragma unroll
                for (int nt = 0; nt < 4; ++nt)
                    mma16816(acc[mt][nt], ah, bw[cur][nt]);
            }

            if (ks == 0 && pf) {
                load_tile(sb, st2, 1, c + 2, bn, tid);
                cp_commit();
            }
        }

        st = (st + 1 == NSTAGE) ? 0 : st + 1;
    }

    // Epilogue: c-frag layout m16n8: lane -> rows l/4, l/4+8; cols 2*(l%4)
    const int rbase = bm * 128 + warpM * 64 + (lane >> 2);
    const int cbase = bn * 128 + warpN * 32 + (lane & 3) * 2;
#pragma unroll
    for (int nt = 0; nt < 4; ++nt) {
        const int col = cbase + nt * 8;
        const float b0 = bias[col], b1 = bias[col + 1];
#pragma unroll
        for (int mt = 0; mt < 4; ++mt) {
            const int row = rbase + mt * 16;
            float2 v0 = make_float2(acc[mt][nt][0] + b0, acc[mt][nt][1] + b1);
            float2 v1 = make_float2(acc[mt][nt][2] + b0, acc[mt][nt][3] + b1);
            *(float2*)(out + (size_t)row * NDIM + col) = v0;
            *(float2*)(out + (size_t)(row + 8) * NDIM + col) = v1;
        }
    }

    // Counter reset for graph replay: the LAST gemm block (all 512 passed the
    // gate by construction) resets both counters.
    __syncthreads();
    if (tid == 0) {
        if (atomicAdd(&g_done, 1) == NB_GEMM - 1) {
            atomicExch(&g_ready, 0);
            atomicExch(&g_done, 0);
        }
    }
}

// ---------------------------------------------------------------------------
extern "C" void kernel_launch(void* const* d_in, const int* in_sizes, int n_in,
                              void* d_out, int out_size) {
    const float* x     = (const float*)d_in[0];
    const float* core0 = (const float*)d_in[1];
    const float* core1 = (const float*)d_in[2];
    const float* core2 = (const float*)d_in[3];
    const float* bias  = (const float*)d_in[4];
    float* out = (float*)d_out;

    cudaFuncSetAttribute(tt_fused,
                         cudaFuncAttributeMaxDynamicSharedMemorySize,
                         SMEM_TOTAL);

    tt_fused<<<NB_ALL, 256, SMEM_TOTAL>>>(x, core0, core1, core2, bias, out);
}

// round 14
// speedup vs baseline: 1.0935x; 1.0935x over previous
#include <cuda_runtime.h>
#include <cuda_fp16.h>
#include <cstdint>

// TensorTrainLinear: out = x @ W + bias.
// Two kernels: (1) compact grid-strided prep (x->fp16 + W build from TT
// cores, fp16 [o][in]); (2) single-product fp16 GEMM (mma.sync m16n8k16,
// fp32 accum), rel_err 2.9e-4 < 1e-3.
// R14: reverts R13 fusion (smem-footprint poisoned prep occupancy). Prep
// compacted to 888 grid-strided blocks; W-build loads core2 smem once and
// loops ~7 units over it. GEMM = R12 (equal-best, 198.4us).

#define KDIM 4096
#define NDIM 4096
#define MDIM 2048

// ---- device scratch (no runtime allocation allowed) ----
__device__ __half g_xh[(size_t)MDIM * KDIM];             // 16 MB
__device__ __half g_wt[(size_t)NDIM * KDIM];             // 32 MB  [o][in]

// ---------------------------------------------------------------------------
// helpers
// ---------------------------------------------------------------------------
__device__ __forceinline__ uint32_t smem_u32(const void* p) {
    uint32_t a;
    asm("{ .reg .u64 t; cvta.to.shared.u64 t, %1; cvt.u32.u64 %0, t; }"
        : "=r"(a) : "l"(p));
    return a;
}

__device__ __forceinline__ void cp16(uint32_t saddr, const void* gaddr) {
    asm volatile("cp.async.cg.shared.global [%0], [%1], 16;\n"
                 :: "r"(saddr), "l"(gaddr));
}
__device__ __forceinline__ void cp_commit() {
    asm volatile("cp.async.commit_group;\n" ::: "memory");
}

__device__ __forceinline__ void ldm4(uint32_t& r0, uint32_t& r1,
                                     uint32_t& r2, uint32_t& r3,
                                     uint32_t addr) {
    asm volatile("ldmatrix.sync.aligned.m8n8.x4.shared.b16 {%0,%1,%2,%3}, [%4];"
                 : "=r"(r0), "=r"(r1), "=r"(r2), "=r"(r3) : "r"(addr));
}

__device__ __forceinline__ void mma16816(float* c, const uint32_t* a,
                                         const uint32_t* b) {
    asm volatile(
        "mma.sync.aligned.m16n8k16.row.col.f32.f16.f16.f32 "
        "{%0,%1,%2,%3}, {%4,%5,%6,%7}, {%8,%9}, {%0,%1,%2,%3};"
        : "+f"(c[0]), "+f"(c[1]), "+f"(c[2]), "+f"(c[3])
        : "r"(a[0]), "r"(a[1]), "r"(a[2]), "r"(a[3]), "r"(b[0]), "r"(b[1]));
}

// ---------------------------------------------------------------------------
// Compact prep: blocks [0,296): grid-stride over 2048 x-convert units
//               blocks [296,888): grid-stride over 4096 W-build units,
//               core2 smem transpose loaded ONCE per block.
// ---------------------------------------------------------------------------
#define NB_XROLE 296
#define NB_WROLE 592
#define NB_PREP  (NB_XROLE + NB_WROLE)

__global__ __launch_bounds__(256) void tt_prep(const float* __restrict__ x,
                                               const float* __restrict__ core0,
                                               const float* __restrict__ core1,
                                               const float* __restrict__ core2) {
    const int tid = threadIdx.x;
    const int bid = blockIdx.x;

    if (bid < NB_XROLE) {
        // ---- x conversion: grid-stride over 2048 units of 4096 floats ----
        for (int u = bid; u < 2048; u += NB_XROLE) {
            const size_t base = ((size_t)u * 256 + tid) * 16;
#pragma unroll
            for (int h = 0; h < 2; ++h) {
                const size_t b8 = base + h * 8;
                float4 v0 = *(const float4*)(x + b8);
                float4 v1 = *(const float4*)(x + b8 + 4);
                float f[8] = {v0.x, v0.y, v0.z, v0.w, v1.x, v1.y, v1.z, v1.w};
                __half hh[8];
#pragma unroll
                for (int i = 0; i < 8; ++i) hh[i] = __float2half(f[i]);
                *(uint4*)(g_xh + b8) = *(uint4*)hh;
            }
        }
        return;
    }

    // ---- W build ----
    __shared__ float s_c2t[4096];   // [r][o3][i3]   (loaded once)
    __shared__ float s_m01[256];    // [i2][r]       (per unit)

    // core2 transposed into smem: src = r*256 + i3*16 + o3 -> [r][o3][i3]
#pragma unroll
    for (int i = 0; i < 16; ++i) {
        const int idx = tid + i * 256;
        const int r = idx >> 8, i3s = (idx >> 4) & 15, o3s = idx & 15;
        s_c2t[r * 256 + o3s * 16 + i3s] = core2[idx];
    }
    __syncthreads();

    const int i2 = tid >> 4, i3 = tid & 15;

    for (int u = bid - NB_XROLE; u < 4096; u += NB_WROLE) {
        const int ohi = u >> 4;                // o1*16 + o2
        const int o2  = ohi & 15;
        const int o1  = ohi >> 4;
        const int i1  = u & 15;
        const int in  = i1 * 256 + i2 * 16 + i3;

        // M01 slice: thread tid = i2s*16 + r (two partial chains).
        // core0 values via broadcast LDG (same address across warp).
        {
            const int i2s = tid >> 4, r = tid & 15;
            const float* c0p = core0 + i1 * 256 + o1 * 16;
            const float* c1p = core1 + i2s * 256 + o2 * 16 + r;
            float a0 = 0.f, a1 = 0.f;
#pragma unroll
            for (int q = 0; q < 16; q += 2) {
                a0 = fmaf(__ldg(c0p + q),     c1p[q * 4096],       a0);
                a1 = fmaf(__ldg(c0p + q + 1), c1p[(q + 1) * 4096], a1);
            }
            s_m01[tid] = a0 + a1;
        }
        __syncthreads();

        float m01[16];
#pragma unroll
        for (int r = 0; r < 16; ++r) m01[r] = s_m01[i2 * 16 + r];

#pragma unroll
        for (int o3 = 0; o3 < 16; ++o3) {
            float a0 = 0.f, a1 = 0.f;
            const float* c2p = s_c2t + o3 * 16 + i3;
#pragma unroll
            for (int r = 0; r < 16; r += 2) {
                a0 = fmaf(m01[r],     c2p[r * 256],       a0);
                a1 = fmaf(m01[r + 1], c2p[(r + 1) * 256], a1);
            }
            g_wt[(size_t)(ohi * 16 + o3) * KDIM + in] = __float2half(a0 + a1);
        }
        __syncthreads();   // s_m01 reuse next unit
    }
}

// ---------------------------------------------------------------------------
// GEMM: out[2048,4096] = xh @ W16 + bias via mma.sync fp16, single product.
// CTA 128x128, BK=64, 8 warps (2x4), warp tile 64x32, 2 CTAs/SM.
// 128B rows, SW128 swizzle (off ^ ((off>>3)&0x70)); 3-stage pipeline,
// one __syncthreads per iteration; B fragments double-buffered across ks;
// A-tile prefetch after barrier, B-tile (+commit) after ks=0.
// ---------------------------------------------------------------------------
#define TILE_BYTES  16384              // 128 rows x 128B
#define STAGE_BYTES (2 * TILE_BYTES)   // 32768 (A, B)
#define NSTAGE      3
#define SMEM_TOTAL  (NSTAGE * STAGE_BYTES)  // 98304

__device__ __forceinline__ void load_tile(uint32_t sb, int stage, int t,
                                          int c, int blk, int tid) {
    const __half* gbase =
        (t == 0 ? g_xh + ((size_t)blk * 128) * KDIM
                : g_wt + ((size_t)blk * 128) * KDIM) + (size_t)c * 64;
    const uint32_t ts = sb + stage * STAGE_BYTES + t * TILE_BYTES;
    const char* gb = (const char*)gbase;
#pragma unroll
    for (int i = 0; i < 4; ++i) {
        const int e   = tid + i * 256;   // 0..1023
        const int row = e >> 3;          // 0..127
        const int seg = e & 7;           // 16B segment in 128B row
        const uint32_t off = row * 128 + seg * 16;
        const uint32_t sw  = off ^ ((off >> 3) & 0x70);
        cp16(ts + sw, gb + (size_t)row * (KDIM * 2) + seg * 16);
    }
}

__global__ void __launch_bounds__(256, 2)
tt_gemm_mma(const float* __restrict__ bias, float* __restrict__ out) {
    extern __shared__ __align__(128) char smem[];
    const uint32_t sb = smem_u32(smem);
    const int tid = threadIdx.x;
    const int lane = tid & 31;
    const int wid = tid >> 5;
    const int warpM = wid >> 2;      // 0..1
    const int warpN = wid & 3;       // 0..3
    const int bn = blockIdx.x, bm = blockIdx.y;

    float acc[4][4][4];
#pragma unroll
    for (int i = 0; i < 4; ++i)
#pragma unroll
        for (int j = 0; j < 4; ++j)
#pragma unroll
            for (int k = 0; k < 4; ++k) acc[i][j][k] = 0.f;

    // SW128: store XORs addr bits 4-6 with row bits 0-2. Load-side:
    // sw = (lane&7) << 4 (all other row terms are multiples of 8).
    const uint32_t sw = (uint32_t)((lane & 7) << 4);
    const uint32_t aRowOff = (uint32_t)(warpM * 64 + (lane & 15)) * 128;
    const uint32_t aColB   = (uint32_t)((lane >> 4) << 4);
    const uint32_t bRowOff =
        (uint32_t)(warpN * 32 + (lane & 7) + ((lane >> 4) & 1) * 8) * 128;
    const uint32_t bColB = (uint32_t)(((lane >> 3) & 1) << 4);

    load_tile(sb, 0, 0, 0, bm, tid);
    load_tile(sb, 0, 1, 0, bn, tid);
    cp_commit();
    load_tile(sb, 1, 0, 1, bm, tid);
    load_tile(sb, 1, 1, 1, bn, tid);
    cp_commit();

    const int KT = KDIM / 64;  // 64
    int st = 0;
    for (int c = 0; c < KT; ++c) {
        if (c + 1 < KT) asm volatile("cp.async.wait_group 1;" ::: "memory");
        else            asm volatile("cp.async.wait_group 0;" ::: "memory");
        __syncthreads();

        const bool pf = (c + 2 < KT);
        int st2 = st + 2; if (st2 >= NSTAGE) st2 -= NSTAGE;
        if (pf) load_tile(sb, st2, 0, c + 2, bm, tid);

        const uint32_t sA = sb + st * STAGE_BYTES;
        const uint32_t sB = sA + TILE_BYTES;

        // B fragments double-buffered across the 4 k-steps
        uint32_t bw[2][4][2];
        {
            const uint32_t bco0 = bColB ^ sw;
#pragma unroll
            for (int np = 0; np < 2; ++np) {
                const uint32_t no = bRowOff + np * 16 * 128 + bco0;
                uint32_t r0, r1, r2, r3;
                ldm4(r0, r1, r2, r3, sB + no);
                bw[0][np * 2][0] = r0; bw[0][np * 2][1] = r1;
                bw[0][np * 2 + 1][0] = r2; bw[0][np * 2 + 1][1] = r3;
            }
        }

#pragma unroll
        for (int ks = 0; ks < 4; ++ks) {
            const int cur = ks & 1;
            const uint32_t aco = (aColB + ks * 32) ^ sw;

            if (ks < 3) {
                const uint32_t bco = (bColB + (ks + 1) * 32) ^ sw;
#pragma unroll
                for (int np = 0; np < 2; ++np) {
                    const uint32_t no = bRowOff + np * 16 * 128 + bco;
                    uint32_t r0, r1, r2, r3;
                    ldm4(r0, r1, r2, r3, sB + no);
                    bw[cur ^ 1][np * 2][0] = r0; bw[cur ^ 1][np * 2][1] = r1;
                    bw[cur ^ 1][np * 2 + 1][0] = r2; bw[cur ^ 1][np * 2 + 1][1] = r3;
                }
            }

#pragma unroll
            for (int mt = 0; mt < 4; ++mt) {
                uint32_t ah[4];
                ldm4(ah[0], ah[1], ah[2], ah[3],
                     sA + aRowOff + mt * 16 * 128 + aco);
#pragma unroll
                for (int nt = 0; nt < 4; ++nt)
                    mma16816(acc[mt][nt], ah, bw[cur][nt]);
            }

            if (ks == 0 && pf) {
                load_tile(sb, st2, 1, c + 2, bn, tid);
                cp_commit();
            }
        }

        st = (st + 1 == NSTAGE) ? 0 : st + 1;
    }

    // Epilogue: c-frag layout m16n8: lane -> rows l/4, l/4+8; cols 2*(l%4)
    const int rbase = bm * 128 + warpM * 64 + (lane >> 2);
    const int cbase = bn * 128 + warpN * 32 + (lane & 3) * 2;
#pragma unroll
    for (int nt = 0; nt < 4; ++nt) {
        const int col = cbase + nt * 8;
        const float b0 = bias[col], b1 = bias[col + 1];
#pragma unroll
        for (int mt = 0; mt < 4; ++mt) {
            const int row = rbase + mt * 16;
            float2 v0 = make_float2(acc[mt][nt][0] + b0, acc[mt][nt][1] + b1);
            float2 v1 = make_float2(acc[mt][nt][2] + b0, acc[mt][nt][3] + b1);
            *(float2*)(out + (size_t)row * NDIM + col) = v0;
            *(float2*)(out + (size_t)(row + 8) * NDIM + col) = v1;
        }
    }
}

// ---------------------------------------------------------------------------
extern "C" void kernel_launch(void* const* d_in, const int* in_sizes, int n_in,
                              void* d_out, int out_size) {
    const float* x     = (const float*)d_in[0];
    const float* core0 = (const float*)d_in[1];
    const float* core1 = (const float*)d_in[2];
    const float* core2 = (const float*)d_in[3];
    const float* bias  = (const float*)d_in[4];
    float* out = (float*)d_out;

    cudaFuncSetAttribute(tt_gemm_mma,
                         cudaFuncAttributeMaxDynamicSharedMemorySize,
                         SMEM_TOTAL);

    tt_prep<<<NB_PREP, 256>>>(x, core0, core1, core2);

    dim3 grid(NDIM / 128, MDIM / 128);  // (32, 16)
    tt_gemm_mma<<<grid, 256, SMEM_TOTAL>>>(bias, out);
}

// round 15
// speedup vs baseline: 1.0982x; 1.0043x over previous
#include <cuda_runtime.h>
#include <cuda_fp16.h>
#include <cstdint>

// TensorTrainLinear: out = x @ W + bias.
// Two kernels: (1) compact grid-strided prep (x->fp16 + W build from TT
// cores, fp16 [o][in]); (2) single-product fp16 GEMM (mma.sync m16n8k16,
// fp32 accum), rel_err 2.9e-4 < 1e-3.
// R15: GEMM identical to R14 (converged: 198.4-198.8us, tensor 66%).
// Prep W-build: s_m01 double-buffered -> ONE __syncthreads per unit.

#define KDIM 4096
#define NDIM 4096
#define MDIM 2048

// ---- device scratch (no runtime allocation allowed) ----
__device__ __half g_xh[(size_t)MDIM * KDIM];             // 16 MB
__device__ __half g_wt[(size_t)NDIM * KDIM];             // 32 MB  [o][in]

// ---------------------------------------------------------------------------
// helpers
// ---------------------------------------------------------------------------
__device__ __forceinline__ uint32_t smem_u32(const void* p) {
    uint32_t a;
    asm("{ .reg .u64 t; cvta.to.shared.u64 t, %1; cvt.u32.u64 %0, t; }"
        : "=r"(a) : "l"(p));
    return a;
}

__device__ __forceinline__ void cp16(uint32_t saddr, const void* gaddr) {
    asm volatile("cp.async.cg.shared.global [%0], [%1], 16;\n"
                 :: "r"(saddr), "l"(gaddr));
}
__device__ __forceinline__ void cp_commit() {
    asm volatile("cp.async.commit_group;\n" ::: "memory");
}

__device__ __forceinline__ void ldm4(uint32_t& r0, uint32_t& r1,
                                     uint32_t& r2, uint32_t& r3,
                                     uint32_t addr) {
    asm volatile("ldmatrix.sync.aligned.m8n8.x4.shared.b16 {%0,%1,%2,%3}, [%4];"
                 : "=r"(r0), "=r"(r1), "=r"(r2), "=r"(r3) : "r"(addr));
}

__device__ __forceinline__ void mma16816(float* c, const uint32_t* a,
                                         const uint32_t* b) {
    asm volatile(
        "mma.sync.aligned.m16n8k16.row.col.f32.f16.f16.f32 "
        "{%0,%1,%2,%3}, {%4,%5,%6,%7}, {%8,%9}, {%0,%1,%2,%3};"
        : "+f"(c[0]), "+f"(c[1]), "+f"(c[2]), "+f"(c[3])
        : "r"(a[0]), "r"(a[1]), "r"(a[2]), "r"(a[3]), "r"(b[0]), "r"(b[1]));
}

// ---------------------------------------------------------------------------
// Compact prep: blocks [0,296): grid-stride over 2048 x-convert units
//               blocks [296,888): grid-stride over 4096 W-build units,
//               core2 smem transpose loaded ONCE; s_m01 double-buffered
//               (one barrier per unit).
// ---------------------------------------------------------------------------
#define NB_XROLE 296
#define NB_WROLE 592
#define NB_PREP  (NB_XROLE + NB_WROLE)

__global__ __launch_bounds__(256) void tt_prep(const float* __restrict__ x,
                                               const float* __restrict__ core0,
                                               const float* __restrict__ core1,
                                               const float* __restrict__ core2) {
    const int tid = threadIdx.x;
    const int bid = blockIdx.x;

    if (bid < NB_XROLE) {
        // ---- x conversion: grid-stride over 2048 units of 4096 floats ----
        for (int u = bid; u < 2048; u += NB_XROLE) {
            const size_t base = ((size_t)u * 256 + tid) * 16;
#pragma unroll
            for (int h = 0; h < 2; ++h) {
                const size_t b8 = base + h * 8;
                float4 v0 = *(const float4*)(x + b8);
                float4 v1 = *(const float4*)(x + b8 + 4);
                float f[8] = {v0.x, v0.y, v0.z, v0.w, v1.x, v1.y, v1.z, v1.w};
                __half hh[8];
#pragma unroll
                for (int i = 0; i < 8; ++i) hh[i] = __float2half(f[i]);
                *(uint4*)(g_xh + b8) = *(uint4*)hh;
            }
        }
        return;
    }

    // ---- W build ----
    __shared__ float s_c2t[4096];      // [r][o3][i3]   (loaded once)
    __shared__ float s_m01[2][256];    // [buf][i2][r]  (double-buffered)

    // core2 transposed into smem: src = r*256 + i3*16 + o3 -> [r][o3][i3]
#pragma unroll
    for (int i = 0; i < 16; ++i) {
        const int idx = tid + i * 256;
        const int r = idx >> 8, i3s = (idx >> 4) & 15, o3s = idx & 15;
        s_c2t[r * 256 + o3s * 16 + i3s] = core2[idx];
    }
    __syncthreads();

    const int i2 = tid >> 4, i3 = tid & 15;
    int buf = 0;

    for (int u = bid - NB_XROLE; u < 4096; u += NB_WROLE) {
        const int ohi = u >> 4;                // o1*16 + o2
        const int o2  = ohi & 15;
        const int o1  = ohi >> 4;
        const int i1  = u & 15;
        const int in  = i1 * 256 + i2 * 16 + i3;

        // M01 slice: thread tid = i2s*16 + r (two partial chains).
        // core0 via broadcast LDG (uniform address across warp).
        {
            const int i2s = tid >> 4, r = tid & 15;
            const float* c0p = core0 + i1 * 256 + o1 * 16;
            const float* c1p = core1 + i2s * 256 + o2 * 16 + r;
            float a0 = 0.f, a1 = 0.f;
#pragma unroll
            for (int q = 0; q < 16; q += 2) {
                a0 = fmaf(__ldg(c0p + q),     c1p[q * 4096],       a0);
                a1 = fmaf(__ldg(c0p + q + 1), c1p[(q + 1) * 4096], a1);
            }
            s_m01[buf][tid] = a0 + a1;
        }
        __syncthreads();   // only barrier per unit (next unit writes buf^1)

        float m01[16];
#pragma unroll
        for (int r = 0; r < 16; ++r) m01[r] = s_m01[buf][i2 * 16 + r];

#pragma unroll
        for (int o3 = 0; o3 < 16; ++o3) {
            float a0 = 0.f, a1 = 0.f;
            const float* c2p = s_c2t + o3 * 16 + i3;
#pragma unroll
            for (int r = 0; r < 16; r += 2) {
                a0 = fmaf(m01[r],     c2p[r * 256],       a0);
                a1 = fmaf(m01[r + 1], c2p[(r + 1) * 256], a1);
            }
            g_wt[(size_t)(ohi * 16 + o3) * KDIM + in] = __float2half(a0 + a1);
        }
        buf ^= 1;
    }
}

// ---------------------------------------------------------------------------
// GEMM: out[2048,4096] = xh @ W16 + bias via mma.sync fp16, single product.
// CTA 128x128, BK=64, 8 warps (2x4), warp tile 64x32, 2 CTAs/SM.
// 128B rows, SW128 swizzle (off ^ ((off>>3)&0x70)); 3-stage pipeline,
// one __syncthreads per iteration; B fragments double-buffered across ks;
// A-tile prefetch after barrier, B-tile (+commit) after ks=0.
// (Converged: identical to R14.)
// ---------------------------------------------------------------------------
#define TILE_BYTES  16384              // 128 rows x 128B
#define STAGE_BYTES (2 * TILE_BYTES)   // 32768 (A, B)
#define NSTAGE      3
#define SMEM_TOTAL  (NSTAGE * STAGE_BYTES)  // 98304

__device__ __forceinline__ void load_tile(uint32_t sb, int stage, int t,
                                          int c, int blk, int tid) {
    const __half* gbase =
        (t == 0 ? g_xh + ((size_t)blk * 128) * KDIM
                : g_wt + ((size_t)blk * 128) * KDIM) + (size_t)c * 64;
    const uint32_t ts = sb + stage * STAGE_BYTES + t * TILE_BYTES;
    const char* gb = (const char*)gbase;
#pragma unroll
    for (int i = 0; i < 4; ++i) {
        const int e   = tid + i * 256;   // 0..1023
        const int row = e >> 3;          // 0..127
        const int seg = e & 7;           // 16B segment in 128B row
        const uint32_t off = row * 128 + seg * 16;
        const uint32_t sw  = off ^ ((off >> 3) & 0x70);
        cp16(ts + sw, gb + (size_t)row * (KDIM * 2) + seg * 16);
    }
}

__global__ void __launch_bounds__(256, 2)
tt_gemm_mma(const float* __restrict__ bias, float* __restrict__ out) {
    extern __shared__ __align__(128) char smem[];
    const uint32_t sb = smem_u32(smem);
    const int tid = threadIdx.x;
    const int lane = tid & 31;
    const int wid = tid >> 5;
    const int warpM = wid >> 2;      // 0..1
    const int warpN = wid & 3;       // 0..3
    const int bn = blockIdx.x, bm = blockIdx.y;

    float acc[4][4][4];
#pragma unroll
    for (int i = 0; i < 4; ++i)
#pragma unroll
        for (int j = 0; j < 4; ++j)
#pragma unroll
            for (int k = 0; k < 4; ++k) acc[i][j][k] = 0.f;

    // SW128: store XORs addr bits 4-6 with row bits 0-2. Load-side:
    // sw = (lane&7) << 4 (all other row terms are multiples of 8).
    const uint32_t sw = (uint32_t)((lane & 7) << 4);
    const uint32_t aRowOff = (uint32_t)(warpM * 64 + (lane & 15)) * 128;
    const uint32_t aColB   = (uint32_t)((lane >> 4) << 4);
    const uint32_t bRowOff =
        (uint32_t)(warpN * 32 + (lane & 7) + ((lane >> 4) & 1) * 8) * 128;
    const uint32_t bColB = (uint32_t)(((lane >> 3) & 1) << 4);

    load_tile(sb, 0, 0, 0, bm, tid);
    load_tile(sb, 0, 1, 0, bn, tid);
    cp_commit();
    load_tile(sb, 1, 0, 1, bm, tid);
    load_tile(sb, 1, 1, 1, bn, tid);
    cp_commit();

    const int KT = KDIM / 64;  // 64
    int st = 0;
    for (int c = 0; c < KT; ++c) {
        if (c + 1 < KT) asm volatile("cp.async.wait_group 1;" ::: "memory");
        else            asm volatile("cp.async.wait_group 0;" ::: "memory");
        __syncthreads();

        const bool pf = (c + 2 < KT);
        int st2 = st + 2; if (st2 >= NSTAGE) st2 -= NSTAGE;
        if (pf) load_tile(sb, st2, 0, c + 2, bm, tid);

        const uint32_t sA = sb + st * STAGE_BYTES;
        const uint32_t sB = sA + TILE_BYTES;

        // B fragments double-buffered across the 4 k-steps
        uint32_t bw[2][4][2];
        {
            const uint32_t bco0 = bColB ^ sw;
#pragma unroll
            for (int np = 0; np < 2; ++np) {
                const uint32_t no = bRowOff + np * 16 * 128 + bco0;
                uint32_t r0, r1, r2, r3;
                ldm4(r0, r1, r2, r3, sB + no);
                bw[0][np * 2][0] = r0; bw[0][np * 2][1] = r1;
                bw[0][np * 2 + 1][0] = r2; bw[0][np * 2 + 1][1] = r3;
            }
        }

#pragma unroll
        for (int ks = 0; ks < 4; ++ks) {
            const int cur = ks & 1;
            const uint32_t aco = (aColB + ks * 32) ^ sw;

            if (ks < 3) {
                const uint32_t bco = (bColB + (ks + 1) * 32) ^ sw;
#pragma unroll
                for (int np = 0; np < 2; ++np) {
                    const uint32_t no = bRowOff + np * 16 * 128 + bco;
                    uint32_t r0, r1, r2, r3;
                    ldm4(r0, r1, r2, r3, sB + no);
                    bw[cur ^ 1][np * 2][0] = r0; bw[cur ^ 1][np * 2][1] = r1;
                    bw[cur ^ 1][np * 2 + 1][0] = r2; bw[cur ^ 1][np * 2 + 1][1] = r3;
                }
            }

#pragma unroll
            for (int mt = 0; mt < 4; ++mt) {
                uint32_t ah[4];
                ldm4(ah[0], ah[1], ah[2], ah[3],
                     sA + aRowOff + mt * 16 * 128 + aco);
#pragma unroll
                for (int nt = 0; nt < 4; ++nt)
                    mma16816(acc[mt][nt], ah, bw[cur][nt]);
            }

            if (ks == 0 && pf) {
                load_tile(sb, st2, 1, c + 2, bn, tid);
                cp_commit();
            }
        }

        st = (st + 1 == NSTAGE) ? 0 : st + 1;
    }

    // Epilogue: c-frag layout m16n8: lane -> rows l/4, l/4+8; cols 2*(l%4)
    const int rbase = bm * 128 + warpM * 64 + (lane >> 2);
    const int cbase = bn * 128 + warpN * 32 + (lane & 3) * 2;
#pragma unroll
    for (int nt = 0; nt < 4; ++nt) {
        const int col = cbase + nt * 8;
        const float b0 = bias[col], b1 = bias[col + 1];
#pragma unroll
        for (int mt = 0; mt < 4; ++mt) {
            const int row = rbase + mt * 16;
            float2 v0 = make_float2(acc[mt][nt][0] + b0, acc[mt][nt][1] + b1);
            float2 v1 = make_float2(acc[mt][nt][2] + b0, acc[mt][nt][3] + b1);
            *(float2*)(out + (size_t)row * NDIM + col) = v0;
            *(float2*)(out + (size_t)(row + 8) * NDIM + col) = v1;
        }
    }
}

// ---------------------------------------------------------------------------
extern "C" void kernel_launch(void* const* d_in, const int* in_sizes, int n_in,
                              void* d_out, int out_size) {
    const float* x     = (const float*)d_in[0];
    const float* core0 = (const float*)d_in[1];
    const float* core1 = (const float*)d_in[2];
    const float* core2 = (const float*)d_in[3];
    const float* bias  = (const float*)d_in[4];
    float* out = (float*)d_out;

    cudaFuncSetAttribute(tt_gemm_mma,
                         cudaFuncAttributeMaxDynamicSharedMemorySize,
                         SMEM_TOTAL);

    tt_prep<<<NB_PREP, 256>>>(x, core0, core1, core2);

    dim3 grid(NDIM / 128, MDIM / 128);  // (32, 16)
    tt_gemm_mma<<<grid, 256, SMEM_TOTAL>>>(bias, out);
}

// round 16
// speedup vs baseline: 1.1209x; 1.0207x over previous
#include <cuda_runtime.h>
#include <cuda_fp16.h>
#include <cstdint>

// TensorTrainLinear: out = x @ W + bias.
// Two kernels: (1) compact grid-strided prep (x->fp16 + W build from TT
// cores, fp16 [o][in]); (2) single-product fp16 GEMM (mma.sync m16n8k16,
// fp32 accum), rel_err 2.9e-4 < 1e-3.
// R16: GEMM byte-identical to R14/R15 (converged 197.6-198.8us).
// Prep W-build software-pipelined: next unit's core0/core1 LDGs issue
// before the current unit's o3/store phase (hides ~500cyc LDG latency).

#define KDIM 4096
#define NDIM 4096
#define MDIM 2048

// ---- device scratch (no runtime allocation allowed) ----
__device__ __half g_xh[(size_t)MDIM * KDIM];             // 16 MB
__device__ __half g_wt[(size_t)NDIM * KDIM];             // 32 MB  [o][in]

// ---------------------------------------------------------------------------
// helpers
// ---------------------------------------------------------------------------
__device__ __forceinline__ uint32_t smem_u32(const void* p) {
    uint32_t a;
    asm("{ .reg .u64 t; cvta.to.shared.u64 t, %1; cvt.u32.u64 %0, t; }"
        : "=r"(a) : "l"(p));
    return a;
}

__device__ __forceinline__ void cp16(uint32_t saddr, const void* gaddr) {
    asm volatile("cp.async.cg.shared.global [%0], [%1], 16;\n"
                 :: "r"(saddr), "l"(gaddr));
}
__device__ __forceinline__ void cp_commit() {
    asm volatile("cp.async.commit_group;\n" ::: "memory");
}

__device__ __forceinline__ void ldm4(uint32_t& r0, uint32_t& r1,
                                     uint32_t& r2, uint32_t& r3,
                                     uint32_t addr) {
    asm volatile("ldmatrix.sync.aligned.m8n8.x4.shared.b16 {%0,%1,%2,%3}, [%4];"
                 : "=r"(r0), "=r"(r1), "=r"(r2), "=r"(r3) : "r"(addr));
}

__device__ __forceinline__ void mma16816(float* c, const uint32_t* a,
                                         const uint32_t* b) {
    asm volatile(
        "mma.sync.aligned.m16n8k16.row.col.f32.f16.f16.f32 "
        "{%0,%1,%2,%3}, {%4,%5,%6,%7}, {%8,%9}, {%0,%1,%2,%3};"
        : "+f"(c[0]), "+f"(c[1]), "+f"(c[2]), "+f"(c[3])
        : "r"(a[0]), "r"(a[1]), "r"(a[2]), "r"(a[3]), "r"(b[0]), "r"(b[1]));
}

// ---------------------------------------------------------------------------
// Compact prep: blocks [0,296): grid-stride over 2048 x-convert units
//               blocks [296,888): grid-stride over 4096 W-build units,
//               core2 smem transpose loaded ONCE; s_m01 double-buffered;
//               next unit's core0/core1 loads pipelined over o3 phase.
// ---------------------------------------------------------------------------
#define NB_XROLE 296
#define NB_WROLE 592
#define NB_PREP  (NB_XROLE + NB_WROLE)

__global__ __launch_bounds__(256) void tt_prep(const float* __restrict__ x,
                                               const float* __restrict__ core0,
                                               const float* __restrict__ core1,
                                               const float* __restrict__ core2) {
    const int tid = threadIdx.x;
    const int bid = blockIdx.x;

    if (bid < NB_XROLE) {
        // ---- x conversion: grid-stride over 2048 units of 4096 floats ----
        for (int u = bid; u < 2048; u += NB_XROLE) {
            const size_t base = ((size_t)u * 256 + tid) * 16;
#pragma unroll
            for (int h = 0; h < 2; ++h) {
                const size_t b8 = base + h * 8;
                float4 v0 = *(const float4*)(x + b8);
                float4 v1 = *(const float4*)(x + b8 + 4);
                float f[8] = {v0.x, v0.y, v0.z, v0.w, v1.x, v1.y, v1.z, v1.w};
                __half hh[8];
#pragma unroll
                for (int i = 0; i < 8; ++i) hh[i] = __float2half(f[i]);
                *(uint4*)(g_xh + b8) = *(uint4*)hh;
            }
        }
        return;
    }

    // ---- W build ----
    __shared__ float s_c2t[4096];      // [r][o3][i3]   (loaded once)
    __shared__ float s_m01[2][256];    // [buf][i2][r]  (double-buffered)

    // core2 transposed into smem: src = r*256 + i3*16 + o3 -> [r][o3][i3]
#pragma unroll
    for (int i = 0; i < 16; ++i) {
        const int idx = tid + i * 256;
        const int r = idx >> 8, i3s = (idx >> 4) & 15, o3s = idx & 15;
        s_c2t[r * 256 + o3s * 16 + i3s] = core2[idx];
    }
    __syncthreads();

    const int i2  = tid >> 4, i3 = tid & 15;   // consumer split
    const int i2s = tid >> 4, r  = tid & 15;   // producer split (same bits)
    int buf = 0;

    // Preload first unit's core0 row + core1 column into registers.
    float c0reg[16], c1reg[16];
    int u = bid - NB_XROLE;
    if (u < 4096) {
        const int ohi = u >> 4, o2 = ohi & 15, o1 = ohi >> 4, i1 = u & 15;
        const float* c0p = core0 + i1 * 256 + o1 * 16;
        const float* c1p = core1 + i2s * 256 + o2 * 16 + r;
#pragma unroll
        for (int q = 0; q < 16; ++q) {
            c0reg[q] = __ldg(c0p + q);
            c1reg[q] = c1p[q * 4096];
        }
    }

    for (; u < 4096; u += NB_WROLE) {
        const int ohi = u >> 4;                // o1*16 + o2
        const int i1  = u & 15;
        const int in  = i1 * 256 + i2 * 16 + i3;

        // M01 slice from preloaded registers (FMA only, two chains)
        {
            float a0 = 0.f, a1 = 0.f;
#pragma unroll
            for (int q = 0; q < 16; q += 2) {
                a0 = fmaf(c0reg[q],     c1reg[q],     a0);
                a1 = fmaf(c0reg[q + 1], c1reg[q + 1], a1);
            }
            s_m01[buf][tid] = a0 + a1;
        }
        __syncthreads();   // only barrier per unit (next unit writes buf^1)

        // Issue next unit's LDGs NOW; latency hides under the o3 phase.
        const int un = u + NB_WROLE;
        if (un < 4096) {
            const int ohin = un >> 4, o2n = ohin & 15, o1n = ohin >> 4;
            const int i1n = un & 15;
            const float* c0p = core0 + i1n * 256 + o1n * 16;
            const float* c1p = core1 + i2s * 256 + o2n * 16 + r;
#pragma unroll
            for (int q = 0; q < 16; ++q) {
                c0reg[q] = __ldg(c0p + q);
                c1reg[q] = c1p[q * 4096];
            }
        }

        float m01[16];
#pragma unroll
        for (int rr = 0; rr < 16; ++rr) m01[rr] = s_m01[buf][i2 * 16 + rr];

#pragma unroll
        for (int o3 = 0; o3 < 16; ++o3) {
            float a0 = 0.f, a1 = 0.f;
            const float* c2p = s_c2t + o3 * 16 + i3;
#pragma unroll
            for (int rr = 0; rr < 16; rr += 2) {
                a0 = fmaf(m01[rr],     c2p[rr * 256],       a0);
                a1 = fmaf(m01[rr + 1], c2p[(rr + 1) * 256], a1);
            }
            g_wt[(size_t)(ohi * 16 + o3) * KDIM + in] = __float2half(a0 + a1);
        }
        buf ^= 1;
    }
}

// ---------------------------------------------------------------------------
// GEMM: out[2048,4096] = xh @ W16 + bias via mma.sync fp16, single product.
// CTA 128x128, BK=64, 8 warps (2x4), warp tile 64x32, 2 CTAs/SM.
// 128B rows, SW128 swizzle (off ^ ((off>>3)&0x70)); 3-stage pipeline,
// one __syncthreads per iteration; B fragments double-buffered across ks;
// A-tile prefetch after barrier, B-tile (+commit) after ks=0.
// (Converged: identical to R14/R15.)
// ---------------------------------------------------------------------------
#define TILE_BYTES  16384              // 128 rows x 128B
#define STAGE_BYTES (2 * TILE_BYTES)   // 32768 (A, B)
#define NSTAGE      3
#define SMEM_TOTAL  (NSTAGE * STAGE_BYTES)  // 98304

__device__ __forceinline__ void load_tile(uint32_t sb, int stage, int t,
                                          int c, int blk, int tid) {
    const __half* gbase =
        (t == 0 ? g_xh + ((size_t)blk * 128) * KDIM
                : g_wt + ((size_t)blk * 128) * KDIM) + (size_t)c * 64;
    const uint32_t ts = sb + stage * STAGE_BYTES + t * TILE_BYTES;
    const char* gb = (const char*)gbase;
#pragma unroll
    for (int i = 0; i < 4; ++i) {
        const int e   = tid + i * 256;   // 0..1023
        const int row = e >> 3;          // 0..127
        const int seg = e & 7;           // 16B segment in 128B row
        const uint32_t off = row * 128 + seg * 16;
        const uint32_t sw  = off ^ ((off >> 3) & 0x70);
        cp16(ts + sw, gb + (size_t)row * (KDIM * 2) + seg * 16);
    }
}

__global__ void __launch_bounds__(256, 2)
tt_gemm_mma(const float* __restrict__ bias, float* __restrict__ out) {
    extern __shared__ __align__(128) char smem[];
    const uint32_t sb = smem_u32(smem);
    const int tid = threadIdx.x;
    const int lane = tid & 31;
    const int wid = tid >> 5;
    const int warpM = wid >> 2;      // 0..1
    const int warpN = wid & 3;       // 0..3
    const int bn = blockIdx.x, bm = blockIdx.y;

    float acc[4][4][4];
#pragma unroll
    for (int i = 0; i < 4; ++i)
#pragma unroll
        for (int j = 0; j < 4; ++j)
#pragma unroll
            for (int k = 0; k < 4; ++k) acc[i][j][k] = 0.f;

    // SW128: store XORs addr bits 4-6 with row bits 0-2. Load-side:
    // sw = (lane&7) << 4 (all other row terms are multiples of 8).
    const uint32_t sw = (uint32_t)((lane & 7) << 4);
    const uint32_t aRowOff = (uint32_t)(warpM * 64 + (lane & 15)) * 128;
    const uint32_t aColB   = (uint32_t)((lane >> 4) << 4);
    const uint32_t bRowOff =
        (uint32_t)(warpN * 32 + (lane & 7) + ((lane >> 4) & 1) * 8) * 128;
    const uint32_t bColB = (uint32_t)(((lane >> 3) & 1) << 4);

    load_tile(sb, 0, 0, 0, bm, tid);
    load_tile(sb, 0, 1, 0, bn, tid);
    cp_commit();
    load_tile(sb, 1, 0, 1, bm, tid);
    load_tile(sb, 1, 1, 1, bn, tid);
    cp_commit();

    const int KT = KDIM / 64;  // 64
    int st = 0;
    for (int c = 0; c < KT; ++c) {
        if (c + 1 < KT) asm volatile("cp.async.wait_group 1;" ::: "memory");
        else            asm volatile("cp.async.wait_group 0;" ::: "memory");
        __syncthreads();

        const bool pf = (c + 2 < KT);
        int st2 = st + 2; if (st2 >= NSTAGE) st2 -= NSTAGE;
        if (pf) load_tile(sb, st2, 0, c + 2, bm, tid);

        const uint32_t sA = sb + st * STAGE_BYTES;
        const uint32_t sB = sA + TILE_BYTES;

        // B fragments double-buffered across the 4 k-steps
        uint32_t bw[2][4][2];
        {
            const uint32_t bco0 = bColB ^ sw;
#pragma unroll
            for (int np = 0; np < 2; ++np) {
                const uint32_t no = bRowOff + np * 16 * 128 + bco0;
                uint32_t r0, r1, r2, r3;
                ldm4(r0, r1, r2, r3, sB + no);
                bw[0][np * 2][0] = r0; bw[0][np * 2][1] = r1;
                bw[0][np * 2 + 1][0] = r2; bw[0][np * 2 + 1][1] = r3;
            }
        }

#pragma unroll
        for (int ks = 0; ks < 4; ++ks) {
            const int cur = ks & 1;
            const uint32_t aco = (aColB + ks * 32) ^ sw;

            if (ks < 3) {
                const uint32_t bco = (bColB + (ks + 1) * 32) ^ sw;
#pragma unroll
                for (int np = 0; np < 2; ++np) {
                    const uint32_t no = bRowOff + np * 16 * 128 + bco;
                    uint32_t r0, r1, r2, r3;
                    ldm4(r0, r1, r2, r3, sB + no);
                    bw[cur ^ 1][np * 2][0] = r0; bw[cur ^ 1][np * 2][1] = r1;
                    bw[cur ^ 1][np * 2 + 1][0] = r2; bw[cur ^ 1][np * 2 + 1][1] = r3;
                }
            }

#pragma unroll
            for (int mt = 0; mt < 4; ++mt) {
                uint32_t ah[4];
                ldm4(ah[0], ah[1], ah[2], ah[3],
                     sA + aRowOff + mt * 16 * 128 + aco);
#pragma unroll
                for (int nt = 0; nt < 4; ++nt)
                    mma16816(acc[mt][nt], ah, bw[cur][nt]);
            }

            if (ks == 0 && pf) {
                load_tile(sb, st2, 1, c + 2, bn, tid);
                cp_commit();
            }
        }

        st = (st + 1 == NSTAGE) ? 0 : st + 1;
    }

    // Epilogue: c-frag layout m16n8: lane -> rows l/4, l/4+8; cols 2*(l%4)
    const int rbase = bm * 128 + warpM * 64 + (lane >> 2);
    const int cbase = bn * 128 + warpN * 32 + (lane & 3) * 2;
#pragma unroll
    for (int nt = 0; nt < 4; ++nt) {
        const int col = cbase + nt * 8;
        const float b0 = bias[col], b1 = bias[col + 1];
#pragma unroll
        for (int mt = 0; mt < 4; ++mt) {
            const int row = rbase + mt * 16;
            float2 v0 = make_float2(acc[mt][nt][0] + b0, acc[mt][nt][1] + b1);
            float2 v1 = make_float2(acc[mt][nt][2] + b0, acc[mt][nt][3] + b1);
            *(float2*)(out + (size_t)row * NDIM + col) = v0;
            *(float2*)(out + (size_t)(row + 8) * NDIM + col) = v1;
        }
    }
}

// ---------------------------------------------------------------------------
extern "C" void kernel_launch(void* const* d_in, const int* in_sizes, int n_in,
                              void* d_out, int out_size) {
    const float* x     = (const float*)d_in[0];
    const float* core0 = (const float*)d_in[1];
    const float* core1 = (const float*)d_in[2];
    const float* core2 = (const float*)d_in[3];
    const float* bias  = (const float*)d_in[4];
    float* out = (float*)d_out;

    cudaFuncSetAttribute(tt_gemm_mma,
                         cudaFuncAttributeMaxDynamicSharedMemorySize,
                         SMEM_TOTAL);

    tt_prep<<<NB_PREP, 256>>>(x, core0, core1, core2);

    dim3 grid(NDIM / 128, MDIM / 128);  // (32, 16)
    tt_gemm_mma<<<grid, 256, SMEM_TOTAL>>>(bias, out);
}